// round 13
// baseline (speedup 1.0000x reference)
#include <cuda_runtime.h>
#include <cstdint>

// Problem constants
#define B_   4
#define H_   384
#define W_   1280
#define GH_  192                 // int(0.5 * 384)
#define N_   (GH_ * W_)          // 245760 ground points per batch
#define HW_  (H_ * W_)           // 491520
#define HYP  25                  // MAX_IT
#define NPTS 5
#define TOLF 0.1f

#define NV_G (N_ / 4)            // 61440 float4 groups per batch (ground)
#define NV_A (HW_ / 4)           // 122880 float4 groups per batch (full)

// k_fit: grid (40, 4) x 512 threads, 3 float4/thread -> 40*512*3 = NV_G exact
#define GA_X  40
#define TA    512
#define FPT_A 3
// k_dist: grid (120, 4) x 256 threads, 4 float4/thread -> 120*256*4 = NV_A exact
#define GB_X  120
#define TB    256
#define FPT_B 4

// Scratch (no cudaMalloc; zero-initialized, self-resetting each run)
__device__ int          g_cnt[B_ * HYP];
__device__ unsigned int g_done[B_];
__device__ float        g_best[B_ * 3];

// ---------------------------------------------------------------------------
// Kernel A: fused solve + count + argmax.
//  - rind LDG issued FIRST (latency hidden under the 9 bulk LDG.128s)
//  - every block redundantly gathers 125 samples (L2-hot) and solves the 25
//    fp64 LS systems in warp 0 (identical results in every block)
//  - PDL trigger so k_dist can begin prefetching into spare SM residency
//  - count 12 points x 25 hyps per thread, warp redux -> smem -> one global
//    atomic per (block, hyp)
//  - ticket: last block per batch does first-max argmax (= jnp.argmax),
//    writes g_best + out_bw, and RESETS g_cnt/g_done for the next replay.
// M = A^T A + 1e-6 added to EVERY entry (matches jnp broadcast).
// ---------------------------------------------------------------------------
__global__ void __launch_bounds__(TA) k_fit(const float* __restrict__ pts,
                                            const int* __restrict__ rind,
                                            float* __restrict__ out_bw) {
    const int b   = blockIdx.y;
    const int tid = threadIdx.x;

    const float* gb = pts + (size_t)b * 3 * HW_ + (size_t)(H_ - GH_) * W_;

    // 1) sample index load first (independent; hides under bulk loads)
    int n = -1;
    if (tid < HYP * NPTS) n = __ldg(rind + b * (HYP * NPTS) + tid);

    // 2) bulk loads: 9 independent LDG.128 per thread
    const float4* xs = (const float4*)gb;
    const float4* ys = xs + (HW_ / 4);
    const float4* zs = xs + 2 * (HW_ / 4);
    const int v0 = blockIdx.x * (TA * FPT_A) + tid;
    float4 X[FPT_A], Y[FPT_A], Z[FPT_A];
#pragma unroll
    for (int i = 0; i < FPT_A; i++) {
        X[i] = xs[v0 + i * TA];
        Y[i] = ys[v0 + i * TA];
        Z[i] = zs[v0 + i * TA];
    }

    __shared__ float sx[HYP * NPTS], sy[HYP * NPTS], sz[HYP * NPTS];
    __shared__ float s_w[HYP * 3];
    __shared__ int   s_c[HYP];

    // 3) dependent sample gathers (rind already in flight)
    if (tid < HYP * NPTS) {
        sx[tid] = __ldg(gb + n);
        sy[tid] = __ldg(gb + HW_ + n);
        sz[tid] = __ldg(gb + 2 * HW_ + n);
    }
    if (tid < HYP) s_c[tid] = 0;
    __syncthreads();

    // 4) solve (threads 0..24 of warp 0, one hypothesis each, fp64)
    if (tid < HYP) {
        int o = tid * NPTS;
        double x0 = sx[o], x1 = sx[o+1], x2 = sx[o+2], x3 = sx[o+3], x4 = sx[o+4];
        double y0 = sy[o], y1 = sy[o+1], y2 = sy[o+2], y3 = sy[o+3], y4 = sy[o+4];
        double z0 = sz[o], z1 = sz[o+1], z2 = sz[o+2], z3 = sz[o+3], z4 = sz[o+4];

        #define PW(e0,e1,e2,e3,e4) (((e0)+(e1)) + (((e2)+(e3)) + (e4)))
        double Sxx = PW(x0*x0, x1*x1, x2*x2, x3*x3, x4*x4);
        double Sxz = PW(x0*z0, x1*z1, x2*z2, x3*z3, x4*z4);
        double Sx  = PW(x0, x1, x2, x3, x4);
        double Szz = PW(z0*z0, z1*z1, z2*z2, z3*z3, z4*z4);
        double Sz  = PW(z0, z1, z2, z3, z4);
        double Sxy = PW(x0*y0, x1*y1, x2*y2, x3*y3, x4*y4);
        double Szy = PW(z0*y0, z1*y1, z2*y2, z3*y3, z4*y4);
        double Sy  = PW(y0, y1, y2, y3, y4);
        #undef PW

        const double e = 1e-6;
        double a  = Sxx + e, bb = Sxz + e, c = Sx + e;
        double d  = Szz + e, f  = Sz  + e;
        double g  = (double)NPTS + e;

        double A00 = d * g - f * f;
        double A01 = c * f - bb * g;
        double A02 = bb * f - c * d;
        double A11 = a * g - c * c;
        double A12 = bb * c - a * f;
        double A22 = a * d - bb * bb;
        double det = (a * A00 + bb * A01) + c * A02;

        // fp32-seeded Newton reciprocal (~2^-46 rel err; outputs are fp32)
        double inv = (double)__frcp_rn((float)det);
        inv = inv * (2.0 - det * inv);
        inv = inv * (2.0 - det * inv);

        double r0 = Sxy, r1 = Szy, r2 = Sy;
        s_w[tid * 3 + 0] = (float)(((A00 * r0 + A01 * r1) + A02 * r2) * inv);
        s_w[tid * 3 + 1] = (float)(((A01 * r0 + A11 * r1) + A12 * r2) * inv);
        s_w[tid * 3 + 2] = (float)(((A02 * r0 + A12 * r1) + A22 * r2) * inv);
    }
    __syncthreads();

    // Let k_dist launch: its blocks prefetch loads in our spare residency
    cudaTriggerProgrammaticLaunchCompletion();

    // 5) count: 12 points x 25 hypotheses per thread
    for (int k = 0; k < HYP; k++) {
        float w0 = s_w[3 * k], w1 = s_w[3 * k + 1], w2 = s_w[3 * k + 2];
        int c = 0;
#pragma unroll
        for (int i = 0; i < FPT_A; i++) {
            c += (fabsf(fmaf(X[i].x, w0, fmaf(Z[i].x, w1, w2)) - Y[i].x) < TOLF);
            c += (fabsf(fmaf(X[i].y, w0, fmaf(Z[i].y, w1, w2)) - Y[i].y) < TOLF);
            c += (fabsf(fmaf(X[i].z, w0, fmaf(Z[i].z, w1, w2)) - Y[i].z) < TOLF);
            c += (fabsf(fmaf(X[i].w, w0, fmaf(Z[i].w, w1, w2)) - Y[i].w) < TOLF);
        }
        unsigned s = __reduce_add_sync(0xffffffffu, (unsigned)c);
        if ((tid & 31) == 0) atomicAdd(&s_c[k], (int)s);
    }
    __syncthreads();
    if (tid < HYP) atomicAdd(&g_cnt[b * HYP + tid], s_c[tid]);
    __syncthreads();

    // 6) ticket: last block per batch -> argmax + reset (deterministic replays)
    if (tid == 0) {
        __threadfence();
        unsigned old = atomicAdd(&g_done[b], 1u);
        if (old == GA_X - 1) {
            __threadfence();
            int best = 0, bc = __ldcg(&g_cnt[b * HYP]);
#pragma unroll
            for (int it = 1; it < HYP; it++) {
                int v = __ldcg(&g_cnt[b * HYP + it]);
                if (v > bc) { bc = v; best = it; }   // first-max = jnp.argmax
            }
            float bw0 = s_w[best * 3 + 0];
            float bw1 = s_w[best * 3 + 1];
            float bw2 = s_w[best * 3 + 2];
            g_best[b * 3 + 0] = bw0;
            g_best[b * 3 + 1] = bw1;
            g_best[b * 3 + 2] = bw2;
            out_bw[b * 3 + 0] = bw0;
            out_bw[b * 3 + 1] = bw1;
            out_bw[b * 3 + 2] = bw2;
            // reset for next graph replay
#pragma unroll
            for (int it = 0; it < HYP; it++) g_cnt[b * HYP + it] = 0;
            g_done[b] = 0;
            __threadfence();
        }
    }
}

// ---------------------------------------------------------------------------
// Kernel B: signed distance over ALL points. PDL-dependent: issue all 12
// LDG.128 first (overlaps k_fit's count phase via spare residency), then
// grid-dependency-sync, then read g_best and store.
// ---------------------------------------------------------------------------
__global__ void __launch_bounds__(TB) k_dist(const float* __restrict__ pts,
                                             float* __restrict__ out) {
    const int b   = blockIdx.y;
    const int tid = threadIdx.x;

    const float4* xs = (const float4*)(pts + (size_t)b * 3 * HW_);
    const float4* ys = xs + (HW_ / 4);
    const float4* zs = xs + 2 * (HW_ / 4);
    float4* o = (float4*)(out + (size_t)b * HW_);

    const int v0 = blockIdx.x * (TB * FPT_B) + tid;
    float4 X[FPT_B], Y[FPT_B], Z[FPT_B];
#pragma unroll
    for (int i = 0; i < FPT_B; i++) {
        X[i] = xs[v0 + i * TB];
        Y[i] = ys[v0 + i * TB];
        Z[i] = zs[v0 + i * TB];
    }

    cudaGridDependencySynchronize();   // k_fit's g_best now visible

    float w0 = g_best[b * 3 + 0];
    float w1 = g_best[b * 3 + 1];
    float w2 = g_best[b * 3 + 2];

#pragma unroll
    for (int i = 0; i < FPT_B; i++) {
        float4 r;
        r.x = fmaf(X[i].x, w0, fmaf(Z[i].x, w1, w2)) - Y[i].x;
        r.y = fmaf(X[i].y, w0, fmaf(Z[i].y, w1, w2)) - Y[i].y;
        r.z = fmaf(X[i].z, w0, fmaf(Z[i].z, w1, w2)) - Y[i].z;
        r.w = fmaf(X[i].w, w0, fmaf(Z[i].w, w1, w2)) - Y[i].w;
        o[v0 + i * TB] = r;
    }
}

// ---------------------------------------------------------------------------
// Launch: 2 kernels, PDL-chained, graph-capturable (no syncs, no allocs).
// Output layout: dist (B*H*W floats) followed by best_w (B*3 floats).
// ---------------------------------------------------------------------------
extern "C" void kernel_launch(void* const* d_in, const int* in_sizes, int n_in,
                              void* d_out, int out_size) {
    const float* pts  = (const float*)d_in[0];
    const int*   rind = (const int*)d_in[1];
    float*       out  = (float*)d_out;

    k_fit<<<dim3(GA_X, B_), TA>>>(pts, rind, out + (size_t)B_ * HW_);

    cudaLaunchAttribute pdl[1];
    pdl[0].id = cudaLaunchAttributeProgrammaticStreamSerialization;
    pdl[0].val.programmaticStreamSerializationAllowed = 1;

    cudaLaunchConfig_t cfg = {};
    cfg.gridDim  = dim3(GB_X, B_);
    cfg.blockDim = dim3(TB);
    cfg.attrs = pdl;
    cfg.numAttrs = 1;
    cudaLaunchKernelEx(&cfg, k_dist, pts, out);
}